// round 8
// baseline (speedup 1.0000x reference)
#include <cuda_runtime.h>

#define N_NODES 4096
#define D_DIM   2048
#define B_SAMP  64
#define BLK     512          // one float4 per thread per row (D/4 = 512)

#define A_T_C    0.3f
#define DSBETA_C 1e-4f
#define E_B_C    0.5f
#define E_N_C    0.005f      // 0.01 * E_B
#define EPS_DS_C 0.01f

// Persistent state across the sequential scan (allocation-free scratch).
__device__ float g_M[(size_t)N_NODES * D_DIM];
__device__ float g_R[(size_t)N_NODES * D_DIM];
__device__ unsigned long long g_best[B_SAMP];
__device__ int g_nb_word32;   // 1 => neighbors stored as 32-bit words, 0 => bytes

__global__ void reset_best_kernel(const unsigned int* __restrict__ nb) {
    if (threadIdx.x < B_SAMP) g_best[threadIdx.x] = 0ULL;
    if (threadIdx.x == 0) {
        // Bool widened to int32 -> words are 0/1; to float32 -> 0/0x3F800000.
        // Raw byte-bools give random packed words; P(all 256 pass) ~ (1/8)^256.
        int w32 = 1;
        for (int i = 0; i < 256; i++) {
            unsigned v = nb[i];
            if (!(v == 0u || v == 1u || v == 0x3F800000u)) { w32 = 0; break; }
        }
        g_nb_word32 = w32;
    }
}

__device__ __forceinline__ void argmax_commit(float act, int n, int slot) {
    // act > 0 always (R > 0) so the float bit pattern is order-preserving.
    // Low word = 0xFFFFFFFF - n: ties pick the SMALLEST node index
    // (matches jnp.argmax first-occurrence semantics).
    unsigned long long key =
        ((unsigned long long)__float_as_uint(act) << 32) |
        (unsigned long long)(0xFFFFFFFFu - (unsigned)n);
    // Pre-filter: stale reads are monotonically <= current value, so skipping
    // when key <= cur is safe and kills most same-address atomic traffic.
    unsigned long long cur = g_best[slot];
    if (key > cur) atomicMax(&g_best[slot], key);
}

// Step-0 activation (no prior update to fuse with).
__global__ __launch_bounds__(BLK) void act_kernel(const float* __restrict__ x,
                                                  const float* __restrict__ W,
                                                  int slot) {
    const int n = blockIdx.x, tid = threadIdx.x;
    const int wrp = tid >> 5, lane = tid & 31;
    float4 w  = ((const float4*)(W   + (size_t)n * D_DIM))[tid];
    float4 r  = ((const float4*)(g_R + (size_t)n * D_DIM))[tid];
    float4 xv = __ldg(((const float4*)x) + tid);
    float d0 = xv.x - w.x, d1 = xv.y - w.y, d2 = xv.z - w.z, d3 = xv.w - w.w;
    float dist = r.x * d0 * d0 + r.y * d1 * d1 + r.z * d2 * d2 + r.w * d3 * d3;
    float rsum = r.x + r.y + r.z + r.w;
#pragma unroll
    for (int o = 16; o > 0; o >>= 1) {
        dist += __shfl_down_sync(0xffffffffu, dist, o);
        rsum += __shfl_down_sync(0xffffffffu, rsum, o);
    }
    __shared__ float sd[16], sr[16];
    if (lane == 0) { sd[wrp] = dist; sr[wrp] = rsum; }
    __syncthreads();
    if (tid == 0) {
        float dt = 0.f, rt = 0.f;
#pragma unroll
        for (int i = 0; i < 16; i++) { dt += sd[i]; rt += sr[i]; }
        argmax_commit(rt / (rt + dt + 1e-7f), n, slot);
    }
}

// Fused: update for sample t (using g_best[t]) then activation for sample t+1.
// Branching is block-uniform (depends only on blockIdx.x), so updated blocks
// keep their new W/R row in registers and feed phase 2 without re-reading.
__global__ __launch_bounds__(BLK) void fused_kernel(const float* __restrict__ xu,
                                                    const float* __restrict__ xa,
                                                    float* __restrict__ W,
                                                    const void* __restrict__ nbv,
                                                    int t, int do_act) {
    const int n = blockIdx.x, tid = threadIdx.x;
    const int wrp = tid >> 5, lane = tid & 31;
    float4* Wr = (float4*)(W   + (size_t)n * D_DIM);
    float4* Mr = (float4*)(g_M + (size_t)n * D_DIM);
    float4* Rr = (float4*)(g_R + (size_t)n * D_DIM);

    __shared__ float sa[16], sb[16], sc[16];
    __shared__ float s_av, s_den;

    // ---- phase 1: update (winner + neighbors only) ----
    const unsigned long long key0 = g_best[t];
    const float pact = __uint_as_float((unsigned)(key0 >> 32));
    float lr = 0.f;
    if (pact >= A_T_C) {   // do_upd; else whole update step is a no-op
        const int winner = (int)(0xFFFFFFFFu - (unsigned)(key0 & 0xFFFFFFFFu));
        if (n == winner) {
            lr = E_B_C;
        } else {
            const size_t idx = (size_t)winner * N_NODES + n;
            bool isnb = g_nb_word32 ? (((const unsigned int*)nbv)[idx] != 0u)
                                    : (((const unsigned char*)nbv)[idx] != 0);
            if (isnb) lr = E_N_C;
        }
    }

    float4 w, r;
    if (lr > 0.f) {
        const float c = lr * DSBETA_C, omc = 1.0f - c;
        float4 wo = Wr[tid];
        float4 m  = __ldcs(Mr + tid);             // M: evict-first (streamed)
        float4 xv = __ldg(((const float4*)xu) + tid);
        float d0 = xv.x - wo.x, d1 = xv.y - wo.y, d2 = xv.z - wo.z, d3 = xv.w - wo.w;
        float4 mn;
        mn.x = c * fabsf(d0) + omc * m.x;
        mn.y = c * fabsf(d1) + omc * m.y;
        mn.z = c * fabsf(d2) + omc * m.z;
        mn.w = c * fabsf(d3) + omc * m.w;
        w.x = wo.x + lr * d0;
        w.y = wo.y + lr * d1;
        w.z = wo.z + lr * d2;
        w.w = wo.w + lr * d3;

        float pmax = fmaxf(fmaxf(mn.x, mn.y), fmaxf(mn.z, mn.w));
        float pmin = fminf(fminf(mn.x, mn.y), fminf(mn.z, mn.w));
        float psum = mn.x + mn.y + mn.z + mn.w;
#pragma unroll
        for (int o = 16; o > 0; o >>= 1) {
            pmax = fmaxf(pmax, __shfl_down_sync(0xffffffffu, pmax, o));
            pmin = fminf(pmin, __shfl_down_sync(0xffffffffu, pmin, o));
            psum +=            __shfl_down_sync(0xffffffffu, psum, o);
        }
        if (lane == 0) { sa[wrp] = pmax; sb[wrp] = pmin; sc[wrp] = psum; }
        __syncthreads();
        if (tid == 0) {
            float mx = -1e30f, mnv = 1e30f, sum = 0.f;
#pragma unroll
            for (int i = 0; i < 16; i++) {
                mx  = fmaxf(mx, sa[i]);
                mnv = fminf(mnv, sb[i]);
                sum += sc[i];
            }
            s_av  = sum / (float)D_DIM;
            s_den = EPS_DS_C * (mx - mnv);
        }
        __syncthreads();
        const float av = s_av, den = s_den;
        if (den == 0.0f) {
            r.x = r.y = r.z = r.w = 1.0f;   // matches reference's NaN->1 path
        } else {
            float a0 = fminf(fmaxf((mn.x - av) / den, -80.0f), 80.0f);
            float a1 = fminf(fmaxf((mn.y - av) / den, -80.0f), 80.0f);
            float a2 = fminf(fmaxf((mn.z - av) / den, -80.0f), 80.0f);
            float a3 = fminf(fmaxf((mn.w - av) / den, -80.0f), 80.0f);
            r.x = 1.0f / (1.0f + expf(a0));
            r.y = 1.0f / (1.0f + expf(a1));
            r.z = 1.0f / (1.0f + expf(a2));
            r.w = 1.0f / (1.0f + expf(a3));
        }
        __stcs(Mr + tid, mn);                     // M: evict-first (streamed)
        Rr[tid] = r;                              // R/W: keep L2-resident
        Wr[tid] = w;
    } else {
        w = Wr[tid];
        r = Rr[tid];
    }

    // ---- phase 2: activation for sample t+1 (uses in-register w/r) ----
    if (!do_act) return;
    float4 xv = __ldg(((const float4*)xa) + tid);
    float d0 = xv.x - w.x, d1 = xv.y - w.y, d2 = xv.z - w.z, d3 = xv.w - w.w;
    float dist = r.x * d0 * d0 + r.y * d1 * d1 + r.z * d2 * d2 + r.w * d3 * d3;
    float rsum = r.x + r.y + r.z + r.w;
#pragma unroll
    for (int o = 16; o > 0; o >>= 1) {
        dist += __shfl_down_sync(0xffffffffu, dist, o);
        rsum += __shfl_down_sync(0xffffffffu, rsum, o);
    }
    if (lane == 0) { sa[wrp] = dist; sb[wrp] = rsum; }
    __syncthreads();
    if (tid == 0) {
        float dt = 0.f, rt = 0.f;
#pragma unroll
        for (int i = 0; i < 16; i++) { dt += sa[i]; rt += sb[i]; }
        argmax_commit(rt / (rt + dt + 1e-7f), n, t + 1);
    }
}

extern "C" void kernel_launch(void* const* d_in, const int* in_sizes, int n_in,
                              void* d_out, int out_size) {
    const float* x          = (const float*)d_in[0];   // [B, D]
    const float* weights    = (const float*)d_in[1];   // [N, D]
    const float* moving_avg = (const float*)d_in[2];   // [N, D]
    const float* relevances = (const float*)d_in[3];   // [N, D]
    // d_in[4] = wins (unused for output)
    const void*  neighbors  = d_in[5];                 // [N, N] bool (width auto-detected)

    float* W = (float*)d_out;

    void *pM = nullptr, *pR = nullptr;
    cudaGetSymbolAddress(&pM, g_M);
    cudaGetSymbolAddress(&pR, g_R);

    const size_t bytes = sizeof(float) * (size_t)N_NODES * D_DIM;
    cudaMemcpyAsync(W,  weights,    bytes, cudaMemcpyDeviceToDevice);
    cudaMemcpyAsync(pM, moving_avg, bytes, cudaMemcpyDeviceToDevice);
    cudaMemcpyAsync(pR, relevances, bytes, cudaMemcpyDeviceToDevice);

    reset_best_kernel<<<1, 64>>>((const unsigned int*)neighbors);

    act_kernel<<<N_NODES, BLK>>>(x, W, 0);
    for (int t = 0; t < B_SAMP; t++) {
        const float* xu = x + (size_t)t * D_DIM;
        const float* xa = x + (size_t)((t + 1 < B_SAMP) ? t + 1 : t) * D_DIM;
        fused_kernel<<<N_NODES, BLK>>>(xu, xa, W, neighbors, t,
                                       (t + 1 < B_SAMP) ? 1 : 0);
    }
}